// round 3
// baseline (speedup 1.0000x reference)
#include <cuda_runtime.h>
#include <cstdint>

// Problem constants
constexpr int T = 512, B = 64, F = 32, K = 32;

constexpr int OFF_SCORE = 0;
constexpr int OFF_MAXS  = 64;                    // [T,B,K] floats
constexpr int OFF_IDX   = 64 + T * B * K;       // [T,B,K] (ints as float)
constexpr int OFF_FEATS = 64 + 2 * T * B * K;   // [T,B,K] floats

#define FULL 0xffffffffu

__device__ __forceinline__ float ex2f(float x) {
    float y; asm("ex2.approx.f32 %0, %1;" : "=f"(y) : "f"(x)); return y;
}
__device__ __forceinline__ float lg2f(float x) {
    float y; asm("lg2.approx.f32 %0, %1;" : "=f"(y) : "f"(x)); return y;
}

constexpr float L2E  = 1.4426950408889634f;
constexpr float LN2  = 0.6931471805599453f;
constexpr float LN32 = 3.4657359027997265f;   // ln(32)

// ---------------------------------------------------------------------------
// Kernel 1: emission feats.  One warp per (t,b); lane = tag k.
// feats[t,b,k] = sum_f W[ idx ],  idx = (t<len[b]) ? words[t,b,f]+k : 0
// Also writes max_s[0] = feats[0] and max_s_idx[0] = 0.
// ---------------------------------------------------------------------------
__global__ void feats_kernel(const int* __restrict__ words,
                             const int* __restrict__ lens,
                             const float* __restrict__ W,
                             float* __restrict__ out) {
    int gw   = (blockIdx.x * blockDim.x + threadIdx.x) >> 5;   // t*B + b
    int lane = threadIdx.x & 31;
    if (gw >= T * B) return;
    int t = gw >> 6;     // / B (B==64)
    int b = gw & 63;

    int L = __ldg(&lens[b]);
    bool valid = (t < L);

    // coalesced: lane f loads word f of this (t,b)
    int w = valid ? __ldg(&words[gw * F + lane]) : 0;

    float s0 = 0.f, s1 = 0.f, s2 = 0.f, s3 = 0.f;
#pragma unroll
    for (int f = 0; f < F; f += 4) {
        int w0 = __shfl_sync(FULL, w, f);
        int w1 = __shfl_sync(FULL, w, f + 1);
        int w2 = __shfl_sync(FULL, w, f + 2);
        int w3 = __shfl_sync(FULL, w, f + 3);
        // index zeroing happens AFTER adding the tag offset in the reference
        int i0 = valid ? (w0 + lane) : 0;
        int i1 = valid ? (w1 + lane) : 0;
        int i2 = valid ? (w2 + lane) : 0;
        int i3 = valid ? (w3 + lane) : 0;
        s0 += __ldg(&W[i0]);
        s1 += __ldg(&W[i1]);
        s2 += __ldg(&W[i2]);
        s3 += __ldg(&W[i3]);
    }
    float s = (s0 + s1) + (s2 + s3);

    out[OFF_FEATS + gw * K + lane] = s;
    if (t == 0) {
        out[OFF_MAXS + b * K + lane] = s;     // max_s[0] = feats[0]
        out[OFF_IDX  + b * K + lane] = 0.f;   // max_s_idx[0] = 0
    }
}

// ---------------------------------------------------------------------------
// Kernel 2: serial recurrence.  grid = 2*B blocks of ONE warp each
// (forward & Viterbi on separate SMs -> no SHFL-unit contention):
//   blocks [0,B)   : forward algorithm, LINEAR domain -> forward_score[b]
//   blocks [B,2B)  : Viterbi max recursion -> max_s[t] for t=1..T-1
// lane = current tag k; tc[j] = trans[j][k] held in registers.
// ---------------------------------------------------------------------------
__global__ void __launch_bounds__(32, 1)
rec_kernel(const float* __restrict__ trans,
           const int* __restrict__ lens,
           float* __restrict__ out) {
    int b    = blockIdx.x & (B - 1);
    int role = blockIdx.x >> 6;
    int lane = threadIdx.x & 31;
    const float* feats = out + OFF_FEATS;
    float* maxs = out + OFF_MAXS;

    int L = __ldg(&lens[b]);

    float tc[K];
#pragma unroll
    for (int j = 0; j < K; j++) tc[j] = __ldg(&trans[j * K + lane]);

    float f0 = feats[b * K + lane];

    if (role == 0) {
        // ------------- forward chain, linear domain -------------
        // state: E_j = exp(alpha_j - Ctot)   (j = lane), Ctot lane-uniform
        float et[K];
#pragma unroll
        for (int j = 0; j < K; j++) et[j] = ex2f(tc[j] * L2E);   // exp(trans)

        float C0   = __shfl_sync(FULL, f0, 0);
        float E    = ex2f((f0 - C0) * L2E);
        float Ctot = C0;

        // prefetch feats 3 deep; xA/xB = exp(f)/32 precomputed off-chain
        float fA = feats[(1 * B + b) * K + lane];
        float fB = feats[(2 * B + b) * K + lane];
        float fC = feats[(3 * B + b) * K + lane];
        float xA = ex2f(fA * L2E - 5.f);
        float xB = ex2f(fB * L2E - 5.f);

        for (int t = 1; t < T; t++) {
            float xf = xA;
            xA = xB;
            fA = fB; fB = fC;
            fC = (t + 3 < T) ? feats[((t + 3) * B + b) * K + lane] : 0.f;
            xB = ex2f(fB * L2E - 5.f);

            float s0 = 0.f, s1 = 0.f, s2 = 0.f, s3 = 0.f;
#pragma unroll
            for (int j = 0; j < K; j += 4) {
                s0 = fmaf(__shfl_sync(FULL, E, j),     et[j],     s0);
                s1 = fmaf(__shfl_sync(FULL, E, j + 1), et[j + 1], s1);
                s2 = fmaf(__shfl_sync(FULL, E, j + 2), et[j + 2], s2);
                s3 = fmaf(__shfl_sync(FULL, E, j + 3), et[j + 3], s3);
            }
            float S  = (s0 + s1) + (s2 + s3);
            float En = S * xf;                 // * exp(f_k)/32
            if (t < L) { E = En; Ctot += LN32; }   // freeze on pad

            if ((t & 31) == 0) {
                // renormalize (alpha-preserving: safe even when frozen)
                float r = __shfl_sync(FULL, E, 0);
                float c = lg2f(r);
                E *= ex2f(-c);
                Ctot += c * LN2;
            }
        }

        // forward_score = Ctot + ln(sum_j E_j)
        float e = E;
#pragma unroll
        for (int o = 16; o; o >>= 1) e += __shfl_xor_sync(FULL, e, o);
        if (lane == 0) out[OFF_SCORE + b] = Ctot + lg2f(e) * LN2;

    } else {
        // ------------------- Viterbi (max) chain -------------------
        const float NEG_INF = __int_as_float(0xff800000);
        float delta = f0;
        float fA = feats[(1 * B + b) * K + lane];
        float fB = feats[(2 * B + b) * K + lane];
        float fC = feats[(3 * B + b) * K + lane];

        for (int t = 1; t < T; t++) {
            float f = fA;
            fA = fB; fB = fC;
            fC = (t + 3 < T) ? feats[((t + 3) * B + b) * K + lane] : 0.f;

            float m0 = NEG_INF, m1 = NEG_INF, m2 = NEG_INF, m3 = NEG_INF;
#pragma unroll
            for (int j = 0; j < K; j += 4) {
                m0 = fmaxf(m0, __shfl_sync(FULL, delta, j)     + tc[j]);
                m1 = fmaxf(m1, __shfl_sync(FULL, delta, j + 1) + tc[j + 1]);
                m2 = fmaxf(m2, __shfl_sync(FULL, delta, j + 2) + tc[j + 2]);
                m3 = fmaxf(m3, __shfl_sync(FULL, delta, j + 3) + tc[j + 3]);
            }
            float dnew = fmaxf(fmaxf(m0, m1), fmaxf(m2, m3)) + f;
            if (t < L) delta = dnew;                      // freeze on pad
            maxs[(t * B + b) * K + lane] = delta;         // post-where value
        }
    }
}

// ---------------------------------------------------------------------------
// Kernel 3: backpointers (parallel).  Warp per (t,b), t in [1,T); lane = k.
// bp[t,b,k] = argmax_j ( max_s[t-1,b,j] + trans[j,k] )   (first index on ties)
// ---------------------------------------------------------------------------
__global__ void bp_kernel(const float* __restrict__ trans,
                          float* __restrict__ out) {
    int gw   = (blockIdx.x * blockDim.x + threadIdx.x) >> 5;
    int lane = threadIdx.x & 31;
    if (gw >= (T - 1) * B) return;
    int t = gw / B + 1;
    int b = gw % B;

    const float* maxs = out + OFF_MAXS;

    float tcj[K];
#pragma unroll
    for (int j = 0; j < K; j++) tcj[j] = __ldg(&trans[j * K + lane]);

    float dprev = maxs[((t - 1) * B + b) * K + lane];   // lane acts as j source

    float best = __shfl_sync(FULL, dprev, 0) + tcj[0];
    int   bi   = 0;
#pragma unroll
    for (int j = 1; j < K; j++) {
        float sc = __shfl_sync(FULL, dprev, j) + tcj[j];
        if (sc > best) { best = sc; bi = j; }           // strict > keeps first
    }
    out[OFF_IDX + (t * B + b) * K + lane] = (float)bi;
}

// ---------------------------------------------------------------------------
extern "C" void kernel_launch(void* const* d_in, const int* in_sizes, int n_in,
                              void* d_out, int out_size) {
    const int*   words = (const int*)d_in[0];     // [T,B,F] int32
    const int*   lens  = (const int*)d_in[1];     // [B] int32
    const float* W     = (const float*)d_in[2];   // [1e6] f32
    const float* trans = (const float*)d_in[3];   // [K,K] f32
    float* out = (float*)d_out;

    feats_kernel<<<(T * B) / 8, 256>>>(words, lens, W, out);
    rec_kernel<<<2 * B, 32>>>(trans, lens, out);
    bp_kernel<<<((T - 1) * B + 7) / 8, 256>>>(trans, out);
}

// round 4
// speedup vs baseline: 1.2959x; 1.2959x over previous
#include <cuda_runtime.h>
#include <cstdint>

// Problem constants
constexpr int T = 512, B = 64, F = 32, K = 32;

constexpr int OFF_SCORE = 0;
constexpr int OFF_MAXS  = 64;                    // [T,B,K] floats
constexpr int OFF_IDX   = 64 + T * B * K;       // [T,B,K] (ints as float)
constexpr int OFF_FEATS = 64 + 2 * T * B * K;   // [T,B,K] floats

#define FULL 0xffffffffu

__device__ __forceinline__ float ex2f(float x) {
    float y; asm("ex2.approx.f32 %0, %1;" : "=f"(y) : "f"(x)); return y;
}
__device__ __forceinline__ float lg2f(float x) {
    float y; asm("lg2.approx.f32 %0, %1;" : "=f"(y) : "f"(x)); return y;
}

constexpr float L2E  = 1.4426950408889634f;
constexpr float LN2  = 0.6931471805599453f;
constexpr float LN32 = 3.4657359027997265f;   // ln(32)

// ---------------------------------------------------------------------------
// Kernel 1: emission feats.  One warp per (t,b); lane = tag k.
// ---------------------------------------------------------------------------
__global__ void feats_kernel(const int* __restrict__ words,
                             const int* __restrict__ lens,
                             const float* __restrict__ W,
                             float* __restrict__ out) {
    int gw   = (blockIdx.x * blockDim.x + threadIdx.x) >> 5;   // t*B + b
    int lane = threadIdx.x & 31;
    if (gw >= T * B) return;
    int t = gw >> 6;     // / B (B==64)
    int b = gw & 63;

    int L = __ldg(&lens[b]);
    bool valid = (t < L);

    int w = valid ? __ldg(&words[gw * F + lane]) : 0;

    float s0 = 0.f, s1 = 0.f, s2 = 0.f, s3 = 0.f;
#pragma unroll
    for (int f = 0; f < F; f += 4) {
        int w0 = __shfl_sync(FULL, w, f);
        int w1 = __shfl_sync(FULL, w, f + 1);
        int w2 = __shfl_sync(FULL, w, f + 2);
        int w3 = __shfl_sync(FULL, w, f + 3);
        int i0 = valid ? (w0 + lane) : 0;   // mask AFTER tag shift (ref semantics)
        int i1 = valid ? (w1 + lane) : 0;
        int i2 = valid ? (w2 + lane) : 0;
        int i3 = valid ? (w3 + lane) : 0;
        s0 += __ldg(&W[i0]);
        s1 += __ldg(&W[i1]);
        s2 += __ldg(&W[i2]);
        s3 += __ldg(&W[i3]);
    }
    float s = (s0 + s1) + (s2 + s3);

    out[OFF_FEATS + gw * K + lane] = s;
    if (t == 0) {
        out[OFF_MAXS + b * K + lane] = s;     // max_s[0] = feats[0]
        out[OFF_IDX  + b * K + lane] = 0.f;   // max_s_idx[0] = 0
    }
}

// ---------------------------------------------------------------------------
// Kernel 2: serial recurrence.  Grid = B blocks, 64 threads (2 warps):
//   warp 0: forward algorithm in LINEAR domain -> forward_score[b]
//   warp 1: Viterbi max recursion -> max_s[t]
// Cross-lane broadcast via double-buffered SMEM + LDS.128 (8 loads vs 32 shfl).
// ---------------------------------------------------------------------------
__global__ void __launch_bounds__(64, 1)
rec_kernel(const float* __restrict__ trans,
           const int* __restrict__ lens,
           float* __restrict__ out) {
    __shared__ float buf[2][2][K];           // [warp][phase][lane]

    int b    = blockIdx.x;
    int wid  = threadIdx.x >> 5;
    int lane = threadIdx.x & 31;
    const float* feats = out + OFF_FEATS;
    float* maxs = out + OFF_MAXS;

    int L = __ldg(&lens[b]);

    float tc[K];                             // trans[j][lane]
#pragma unroll
    for (int j = 0; j < K; j++) tc[j] = __ldg(&trans[j * K + lane]);

    float f0 = feats[b * K + lane];

    if (wid == 0) {
        // ---------- forward chain, linear domain ----------
        // state: E_j = exp(alpha_j - Ctot), Ctot lane-uniform
        float et[K];
#pragma unroll
        for (int j = 0; j < K; j++) et[j] = ex2f(tc[j] * L2E);   // exp(trans)

        float C0   = __shfl_sync(FULL, f0, 0);
        float E    = ex2f((f0 - C0) * L2E);
        float Ctot = C0;

        float fA = feats[(1 * B + b) * K + lane];
        float fB = feats[(2 * B + b) * K + lane];
        float fC = feats[(3 * B + b) * K + lane];
        float xA = ex2f(fA * L2E - 5.f);     // exp(f)/32, precomputed off-chain
        float xB = ex2f(fB * L2E - 5.f);

        for (int t = 1; t < T; t++) {
            float xf = xA;
            xA = xB;
            fA = fB; fB = fC;
            fC = (t + 3 < T) ? feats[((t + 3) * B + b) * K + lane] : 0.f;
            xB = ex2f(fB * L2E - 5.f);

            int ph = t & 1;
            buf[0][ph][lane] = E;
            __syncwarp();
            const float4* b4 = reinterpret_cast<const float4*>(buf[0][ph]);

            float s0 = 0.f, s1 = 0.f, s2 = 0.f, s3 = 0.f;
#pragma unroll
            for (int q = 0; q < 8; q += 4) {
                float4 v0 = b4[q], v1 = b4[q + 1], v2 = b4[q + 2], v3 = b4[q + 3];
                int j = q * 4;
                s0 = fmaf(v0.x, et[j+0],  s0); s1 = fmaf(v0.y, et[j+1],  s1);
                s2 = fmaf(v0.z, et[j+2],  s2); s3 = fmaf(v0.w, et[j+3],  s3);
                s0 = fmaf(v1.x, et[j+4],  s0); s1 = fmaf(v1.y, et[j+5],  s1);
                s2 = fmaf(v1.z, et[j+6],  s2); s3 = fmaf(v1.w, et[j+7],  s3);
                s0 = fmaf(v2.x, et[j+8],  s0); s1 = fmaf(v2.y, et[j+9],  s1);
                s2 = fmaf(v2.z, et[j+10], s2); s3 = fmaf(v2.w, et[j+11], s3);
                s0 = fmaf(v3.x, et[j+12], s0); s1 = fmaf(v3.y, et[j+13], s1);
                s2 = fmaf(v3.z, et[j+14], s2); s3 = fmaf(v3.w, et[j+15], s3);
            }
            float S  = (s0 + s1) + (s2 + s3);
            float En = S * xf;                       // * exp(f_k)/32
            if (t < L) { E = En; Ctot += LN32; }     // freeze on pad

            if ((t & 31) == 0) {                     // renormalize (alpha-preserving)
                float r = __shfl_sync(FULL, E, 0);
                float c = lg2f(r);
                E *= ex2f(-c);
                Ctot += c * LN2;
            }
        }

        // forward_score = Ctot + ln(sum_j E_j)
        float e = E;
#pragma unroll
        for (int o = 16; o; o >>= 1) e += __shfl_xor_sync(FULL, e, o);
        if (lane == 0) out[OFF_SCORE + b] = Ctot + lg2f(e) * LN2;

    } else {
        // ---------- Viterbi (max) chain ----------
        const float NEG_INF = __int_as_float(0xff800000);
        float delta = f0;
        float fA = feats[(1 * B + b) * K + lane];
        float fB = feats[(2 * B + b) * K + lane];
        float fC = feats[(3 * B + b) * K + lane];

        for (int t = 1; t < T; t++) {
            float f = fA;
            fA = fB; fB = fC;
            fC = (t + 3 < T) ? feats[((t + 3) * B + b) * K + lane] : 0.f;

            int ph = t & 1;
            buf[1][ph][lane] = delta;
            __syncwarp();
            const float4* b4 = reinterpret_cast<const float4*>(buf[1][ph]);

            float m0 = NEG_INF, m1 = NEG_INF, m2 = NEG_INF, m3 = NEG_INF;
#pragma unroll
            for (int q = 0; q < 8; q++) {
                float4 v = b4[q];
                int j = q * 4;
                m0 = fmaxf(m0, v.x + tc[j+0]);
                m1 = fmaxf(m1, v.y + tc[j+1]);
                m2 = fmaxf(m2, v.z + tc[j+2]);
                m3 = fmaxf(m3, v.w + tc[j+3]);
            }
            float dnew = fmaxf(fmaxf(m0, m1), fmaxf(m2, m3)) + f;
            if (t < L) delta = dnew;                  // freeze on pad
            maxs[(t * B + b) * K + lane] = delta;     // post-where value
        }
    }
}

// ---------------------------------------------------------------------------
// Kernel 3: backpointers (parallel).  Warp per (t,b), t in [1,T); lane = k.
// bp[t,b,k] = argmax_j ( max_s[t-1,b,j] + trans[j,k] )   (first index on ties)
// ---------------------------------------------------------------------------
__global__ void bp_kernel(const float* __restrict__ trans,
                          float* __restrict__ out) {
    int gw   = (blockIdx.x * blockDim.x + threadIdx.x) >> 5;
    int lane = threadIdx.x & 31;
    if (gw >= (T - 1) * B) return;
    int t = gw / B + 1;
    int b = gw % B;

    const float* maxs = out + OFF_MAXS;

    float tcj[K];
#pragma unroll
    for (int j = 0; j < K; j++) tcj[j] = __ldg(&trans[j * K + lane]);

    float dprev = maxs[((t - 1) * B + b) * K + lane];

    float best = __shfl_sync(FULL, dprev, 0) + tcj[0];
    int   bi   = 0;
#pragma unroll
    for (int j = 1; j < K; j++) {
        float sc = __shfl_sync(FULL, dprev, j) + tcj[j];
        if (sc > best) { best = sc; bi = j; }       // strict > keeps first index
    }
    out[OFF_IDX + (t * B + b) * K + lane] = (float)bi;
}

// ---------------------------------------------------------------------------
extern "C" void kernel_launch(void* const* d_in, const int* in_sizes, int n_in,
                              void* d_out, int out_size) {
    const int*   words = (const int*)d_in[0];     // [T,B,F] int32
    const int*   lens  = (const int*)d_in[1];     // [B] int32
    const float* W     = (const float*)d_in[2];   // [1e6] f32
    const float* trans = (const float*)d_in[3];   // [K,K] f32
    float* out = (float*)d_out;

    feats_kernel<<<(T * B) / 8, 256>>>(words, lens, W, out);
    rec_kernel<<<B, 64>>>(trans, lens, out);
    bp_kernel<<<((T - 1) * B + 7) / 8, 256>>>(trans, out);
}